// round 1
// baseline (speedup 1.0000x reference)
#include <cuda_runtime.h>

#define IMG 512
#define TW 64
#define TH 32
#define KS 11
#define HALO 5
#define COLS (TW + 2*HALO)   /* 74 */
#define ROWS (TH + 2*HALO)   /* 42 */
#define STRIDE 75            /* padded row stride in float2 (odd -> conflict-free LDS.64) */
#define NTHREADS 256
#define SMEM_BYTES ((ROWS*STRIDE + 2*TH*STRIDE)*8 + TH*STRIDE*4)  /* 73200 B */

typedef unsigned long long u64;

__device__ double g_accum;
__device__ float g_wv[2][KS];
__device__ float g_wh[2][KS];

__device__ __forceinline__ u64 pack2(float x, float y) {
    u64 r; asm("mov.b64 %0, {%1,%2};" : "=l"(r) : "f"(x), "f"(y)); return r;
}
__device__ __forceinline__ void unpack2(u64 v, float& x, float& y) {
    asm("mov.b64 {%0,%1}, %2;" : "=f"(x), "=f"(y) : "l"(v));
}
__device__ __forceinline__ u64 fma2(u64 a, u64 b, u64 c) {
    u64 d; asm("fma.rn.f32x2 %0, %1, %2, %3;" : "=l"(d) : "l"(a), "l"(b), "l"(c)); return d;
}
__device__ __forceinline__ u64 mul2(u64 a, u64 b) {
    u64 d; asm("mul.rn.f32x2 %0, %1, %2;" : "=l"(d) : "l"(a), "l"(b)); return d;
}

// Rebuild separable 1D factors from the 2D Gaussian (rank-1): k[i][j] = r[i]*c[j]/T
__global__ void prep_kernel(const float* __restrict__ kern) {
    if (threadIdx.x == 0) {
        g_accum = 0.0;
        for (int c = 0; c < 2; c++) {
            const float* k = kern + c * KS * KS;
            float T = 0.f;
            for (int i = 0; i < KS * KS; i++) T += k[i];
            for (int i = 0; i < KS; i++) {
                float r = 0.f;
                for (int j = 0; j < KS; j++) r += k[i * KS + j];
                g_wv[c][i] = r;
            }
            float invT = 1.0f / T;
            for (int j = 0; j < KS; j++) {
                float s = 0.f;
                for (int i = 0; i < KS; i++) s += k[i * KS + j];
                g_wh[c][j] = s * invT;
            }
        }
    }
}

extern __shared__ float2 smem_dyn[];

__global__ __launch_bounds__(NTHREADS)
void ssim_kernel(const float* __restrict__ x, const float* __restrict__ y) {
    float2* s_in = smem_dyn;                       // ROWS x STRIDE (x,y packed)
    float2* s_v1 = s_in + ROWS * STRIDE;           // TH x STRIDE (sx,sy)
    float2* s_v2 = s_v1 + TH * STRIDE;             // TH x STRIDE (sxx,syy)
    float*  s_v3 = (float*)(s_v2 + TH * STRIDE);   // TH x STRIDE (sxy)

    const int tid = threadIdx.x;
    const int plane = blockIdx.z;       // 64 planes = 32 batch * 2 chan, NCHW contiguous
    const int ch = plane & 1;
    const int oh0 = blockIdx.y * TH;
    const int ow0 = blockIdx.x * TW;
    const float* xp = x + (size_t)plane * IMG * IMG;
    const float* yp = y + (size_t)plane * IMG * IMG;

    // ---- stage 0: load input tile (zero-padded halo) ----
    for (int idx = tid; idx < ROWS * COLS; idx += NTHREADS) {
        int tr = idx / COLS, tc = idx - tr * COLS;
        int gr = oh0 + tr - HALO, gc = ow0 + tc - HALO;
        float vx = 0.f, vy = 0.f;
        if ((unsigned)gr < (unsigned)IMG && (unsigned)gc < (unsigned)IMG) {
            int off = gr * IMG + gc;
            vx = __ldg(xp + off); vy = __ldg(yp + off);
        }
        s_in[tr * STRIDE + tc] = make_float2(vx, vy);
    }

    float wvs[KS]; u64 wv2[KS];
    #pragma unroll
    for (int k = 0; k < KS; k++) { wvs[k] = g_wv[ch][k]; wv2[k] = pack2(wvs[k], wvs[k]); }

    __syncthreads();

    // ---- stage 1: vertical conv, 8 output rows per column task (register streaming) ----
    for (int task = tid; task < COLS * (TH / 8); task += NTHREADS) {
        int col = task % COLS;
        int rg = (task / COLS) * 8;
        u64 a1[8], a2[8]; float a3[8];
        #pragma unroll
        for (int i = 0; i < 8; i++) { a1[i] = 0ull; a2[i] = 0ull; a3[i] = 0.f; }
        #pragma unroll
        for (int t = 0; t < 18; t++) {
            u64 u = *reinterpret_cast<const u64*>(&s_in[(rg + t) * STRIDE + col]);
            float ux, uy; unpack2(u, ux, uy);
            u64 v = mul2(u, u);
            float pxy = ux * uy;
            #pragma unroll
            for (int i = 0; i < 8; i++) {
                int k = t - i;
                if (k >= 0 && k < KS) {
                    a1[i] = fma2(wv2[k], u, a1[i]);
                    a2[i] = fma2(wv2[k], v, a2[i]);
                    a3[i] = fmaf(wvs[k], pxy, a3[i]);
                }
            }
        }
        #pragma unroll
        for (int i = 0; i < 8; i++) {
            *reinterpret_cast<u64*>(&s_v1[(rg + i) * STRIDE + col]) = a1[i];
            *reinterpret_cast<u64*>(&s_v2[(rg + i) * STRIDE + col]) = a2[i];
            s_v3[(rg + i) * STRIDE + col] = a3[i];
        }
    }

    float whs[KS]; u64 wh2[KS];
    #pragma unroll
    for (int k = 0; k < KS; k++) { whs[k] = g_wh[ch][k]; wh2[k] = pack2(whs[k], whs[k]); }

    __syncthreads();

    // ---- stage 2: horizontal conv, 8 consecutive px per thread (register streaming) ----
    const int row = tid & 31;        // warp lanes span 32 rows -> conflict-free LDS.64 (odd stride)
    const int c0 = (tid >> 5) * 8;
    u64 h1[8], h2[8]; float h3[8];
    #pragma unroll
    for (int p = 0; p < 8; p++) { h1[p] = 0ull; h2[p] = 0ull; h3[p] = 0.f; }
    #pragma unroll
    for (int j = 0; j < 18; j++) {
        u64 b1 = *reinterpret_cast<const u64*>(&s_v1[row * STRIDE + c0 + j]);
        u64 b2 = *reinterpret_cast<const u64*>(&s_v2[row * STRIDE + c0 + j]);
        float b3 = s_v3[row * STRIDE + c0 + j];
        #pragma unroll
        for (int p = 0; p < 8; p++) {
            int k = j - p;
            if (k >= 0 && k < KS) {
                h1[p] = fma2(wh2[k], b1, h1[p]);
                h2[p] = fma2(wh2[k], b2, h2[p]);
                h3[p] = fmaf(whs[k], b3, h3[p]);
            }
        }
    }

    // ---- epilogue: SSIM per pixel + local sum ----
    float lsum = 0.f;
    const float C1 = 1e-4f, C2 = 9e-4f;
    #pragma unroll
    for (int p = 0; p < 8; p++) {
        float mux, muy; unpack2(h1[p], mux, muy);
        float ex2, ey2; unpack2(h2[p], ex2, ey2);
        float exy = h3[p];
        float mux2 = mux * mux, muy2 = muy * muy, muxy = mux * muy;
        float sx = ex2 - mux2, sy = ey2 - muy2, sxy = exy - muxy;
        float num = (2.f * muxy + C1) * (2.f * sxy + C2);
        float den = (mux2 + muy2 + C1) * (sx + sy + C2);
        lsum += __fdividef(num, den);
    }

    // ---- reduction: warp shuffle -> block -> one double atomic per block ----
    #pragma unroll
    for (int o = 16; o > 0; o >>= 1) lsum += __shfl_xor_sync(0xffffffffu, lsum, o);
    __shared__ float wsum[NTHREADS / 32];
    if ((tid & 31) == 0) wsum[tid >> 5] = lsum;
    __syncthreads();
    if (tid == 0) {
        float b = 0.f;
        #pragma unroll
        for (int w = 0; w < NTHREADS / 32; w++) b += wsum[w];
        atomicAdd(&g_accum, (double)b);
    }
}

__global__ void finalize_kernel(float* __restrict__ out) {
    if (threadIdx.x == 0) {
        out[0] = 1.0f - (float)(g_accum * (1.0 / (32.0 * 2.0 * 512.0 * 512.0)));
    }
}

extern "C" void kernel_launch(void* const* d_in, const int* in_sizes, int n_in,
                              void* d_out, int out_size) {
    const float* x = (const float*)d_in[0];
    const float* y = (const float*)d_in[1];
    const float* kern = (const float*)d_in[2];
    float* out = (float*)d_out;

    cudaFuncSetAttribute(ssim_kernel, cudaFuncAttributeMaxDynamicSharedMemorySize, SMEM_BYTES);

    prep_kernel<<<1, 32>>>(kern);
    dim3 grid(IMG / TW, IMG / TH, 64);
    ssim_kernel<<<grid, NTHREADS, SMEM_BYTES>>>(x, y);
    finalize_kernel<<<1, 32>>>(out);
}